// round 12
// baseline (speedup 1.0000x reference)
#include <cuda_runtime.h>
#include <cuda_fp16.h>
#include <cstdint>

// ============================================================================
// BCQLinear: y = (x[:, in_reorder] @ dequant(qweight))[:, out_reorder]
// M=128, K=N=4096, WBITS=3, GS=OFI=128.
// R12: alpha folded into B (B' = fp16(q'·alpha), HMUL2; accS eliminated ->
//   MMA accumulates straight into accT), A staged in smem via cp.async
//   (LDS 29cyc vs L2 LDG 240cyc), NSPLIT=8 + __launch_bounds__(256,3) for
//   ~2x occupancy. y = sum_g [ MMA(x, q'·a) + (a+b)·Xsum ].
// ============================================================================

#define M_TOK   128
#define IN_F    4096
#define OUT_F   4096
#define NGRP    32
#define NPLANE  8

// Scratch (static __device__ — no allocations)
__device__ uint4    g_xa[NGRP * 8 * 8 * 32];             // 1 MB  A frags (fp16)
__device__ uint32_t g_qb[1024 * 4096];                   // 16 MB B bytes, frag order
__device__ float    g_xsum[NGRP * M_TOK];                // 16 KB group row-sums
__device__ float    g_t_part[NPLANE * M_TOK * OUT_F];    // 16 MB K-split partials
__device__ float    g_t_sum[M_TOK * OUT_F];              // 2 MB  reduced sum

__device__ __forceinline__ uint32_t smem_u32(const void* p) {
    uint32_t a;
    asm("{ .reg .u64 t; cvta.to.shared.u64 t, %1; cvt.u32.u64 %0, t; }"
        : "=r"(a) : "l"(p));
    return a;
}
__device__ __forceinline__ void cp_async16(uint32_t saddr, const void* gptr) {
    asm volatile("cp.async.cg.shared.global [%0], [%1], 16;"
                 :: "r"(saddr), "l"(gptr));
}
#define CP_COMMIT() asm volatile("cp.async.commit_group;" ::: "memory")
#define CP_WAIT0()  asm volatile("cp.async.wait_group 0;" ::: "memory")

// spread 8 bits so bit t lands at bit 4t
__device__ __forceinline__ uint32_t spread8(uint32_t x) {
    x = (x | (x << 12)) & 0x000F000Fu;
    x = (x | (x << 6))  & 0x03030303u;
    x = (x | (x << 3))  & 0x11111111u;
    return x;
}

// fp16 LUT for q' = 2v-8, v=0..7: {-8,-6,-4,-2,0,2,4,6}
//   hi bytes: C8 C6 C4 C0 | 00 40 44 46 ; lo bytes all 0x00.
#define QLUT_A 0xC0C4C6C8u
#define QLUT_B 0x46444000u

// ---------------------------------------------------------------------------
// Kernel 1: gather x[:, in_reorder] -> fp16 A fragments (m16n8k16).
// g_xa[((g*8+ks)*8+mtile)*32 + lane] = {a0,a1,a2,a3}
// ---------------------------------------------------------------------------
__global__ __launch_bounds__(256)
void prep_x_kernel(const float* __restrict__ x, const int* __restrict__ in_reorder) {
    const int t    = blockIdx.x * 256 + threadIdx.x;     // 65536 threads
    const int lane = t & 31;
    const int mt   = (t >> 5) & 7;
    const int ks   = (t >> 8) & 7;
    const int g    = t >> 11;
    const int r0   = mt * 16 + (lane >> 2);
    const int kb   = g * 128 + ks * 16 + (lane & 3) * 2;
    const int kk[4] = { kb, kb + 1, kb + 8, kb + 9 };
    uint32_t hi[4] = {0, 0, 0, 0};
    #pragma unroll
    for (int j = 0; j < 4; j++) {
        const int p = __ldg(&in_reorder[kk[j]]);
        const __half ha = __float2half_rn(x[ r0      * IN_F + p]);
        const __half hb = __float2half_rn(x[(r0 + 8) * IN_F + p]);
        const int reg = (j >> 1) * 2;
        const int sh  = (j & 1) * 16;
        hi[reg]     |= (uint32_t)__half_as_ushort(ha) << sh;
        hi[reg + 1] |= (uint32_t)__half_as_ushort(hb) << sh;
    }
    g_xa[((g * 8 + ks) * 8 + mt) * 32 + lane] = make_uint4(hi[0], hi[1], hi[2], hi[3]);
}

// ---------------------------------------------------------------------------
// Kernel 2: Xsum[g][m] = sum_{k in group g} x[m][in_reorder[k]]
// ---------------------------------------------------------------------------
__global__ __launch_bounds__(256)
void xsum_kernel(const float* __restrict__ x, const int* __restrict__ in_reorder) {
    const int m    = blockIdx.x;
    const int tid  = threadIdx.x;
    const int g    = tid >> 3;
    const int part = tid & 7;
    float s = 0.f;
    #pragma unroll
    for (int j = 0; j < 16; j++)
        s += x[m * IN_F + __ldg(&in_reorder[g * 128 + part * 16 + j])];
    s += __shfl_xor_sync(0xffffffffu, s, 1);
    s += __shfl_xor_sync(0xffffffffu, s, 2);
    s += __shfl_xor_sync(0xffffffffu, s, 4);
    if (part == 0) g_xsum[g * 128 + m] = s;
}

// ---------------------------------------------------------------------------
// Kernel 3: repack bit-planes -> BYTE layout in B-frag order (as R11).
// ---------------------------------------------------------------------------
__global__ __launch_bounds__(256)
void repack_kernel(const int* __restrict__ qweight, const int* __restrict__ offset) {
    const int t    = blockIdx.x * 256 + threadIdx.x;     // 131072
    const int nq   = t & 3;
    const int r    = (t >> 2) & 3;
    const int ks   = (t >> 4) & 7;
    const int tile = t >> 7;                             // g*32 + nb
    const int* src = qweight + __ldg(&offset[tile]);

    uint32_t p0[4], p1[4], p2[4];
    #pragma unroll
    for (int ki = 0; ki < 4; ki++) {
        const int i    = ks * 16 + 2 * r + (ki & 1) + ((ki >> 1) << 3);
        const int widx = i * 4 + nq;
        p0[ki] = (uint32_t)__ldg(src + widx);
        p1[ki] = (uint32_t)__ldg(src + widx + 512);
        p2[ki] = (uint32_t)__ldg(src + widx + 1024);
    }
    uint32_t nib[4][4];
    #pragma unroll
    for (int nt = 0; nt < 4; nt++)
        #pragma unroll
        for (int ki = 0; ki < 4; ki++)
            nib[nt][ki] = spread8((p0[ki] >> (nt * 8)) & 0xFFu)
                        | (spread8((p1[ki] >> (nt * 8)) & 0xFFu) << 1)
                        | (spread8((p2[ki] >> (nt * 8)) & 0xFFu) << 2);

    uint4* dst = ((uint4*)g_qb) + tile * 1024;
    const int cbase = (((ks * 4 + r) * 8) << 2) + ((nq + r) & 3);
    #pragma unroll
    for (int o = 0; o < 8; o++) {
        uint32_t wds[4];
        #pragma unroll
        for (int nt = 0; nt < 4; nt++)
            wds[nt] = ((nib[nt][0] >> (4 * o)) & 0xFu)
                    | (((nib[nt][1] >> (4 * o)) & 0xFu) << 8)
                    | (((nib[nt][2] >> (4 * o)) & 0xFu) << 16)
                    | (((nib[nt][3] >> (4 * o)) & 0xFu) << 24);
        dst[cbase + o * 4] = make_uint4(wds[0], wds[1], wds[2], wds[3]);
    }
}

// ---------------------------------------------------------------------------
// Kernel 4: fp16 GEMM, alpha folded into B, A+B both in smem.
// grid (32 nb, 16 = mhalf*8+split), 256 thr, 3 CTA/SM cap, 64KB dyn smem.
// smem: A buf0/buf1 @ 0/16K, B buf0/buf1 @ 32K/48K.
// ---------------------------------------------------------------------------
#define SMA_OFF(b) ((b) * 16384)
#define SMB_OFF(b) (32768 + (b) * 16384)

__global__ __launch_bounds__(256, 3)
void bcq_gemm_kernel(const float* __restrict__ alpha,
                     const float* __restrict__ beta)
{
    extern __shared__ char sm[];
    const uint32_t smb = smem_u32(sm);
    const int tid  = threadIdx.x;
    const int lane = tid & 31;
    const int wid  = tid >> 5;
    const int nb    = blockIdx.x;
    const int mhalf = blockIdx.y >> 3;
    const int split = blockIdx.y & 7;
    const int wm = wid & 1;
    const int nq = wid >> 1;
    const int r = lane & 3, o = lane >> 2;
    const int boff16 = ((r * 8 + o) << 2) + ((nq + r) & 3);   // uint4 units, cf-free
    // per-thread cp.async source/dest components
    const int aks = tid >> 5, au = tid & 31;

    float accT[2][4][4];
    #pragma unroll
    for (int a = 0; a < 2; a++)
        #pragma unroll
        for (int b = 0; b < 4; b++)
            #pragma unroll
            for (int c = 0; c < 4; c++) accT[a][b][c] = 0.f;

    // prologue: group 0 A (16KB) + B (16KB) tiles
    {
        const int g0 = split * 4;
        const uint4* asrc = g_xa + ((g0 * 8 + aks) * 8 + mhalf * 4) * 32 + au * 4;
        const uint32_t ad = smb + SMA_OFF(0) + aks * 2048 + au * 64;
        cp_async16(ad,      asrc);
        cp_async16(ad + 16, asrc + 1);
        cp_async16(ad + 32, asrc + 2);
        cp_async16(ad + 48, asrc + 3);
        const uint32_t* bsrc = g_qb + (size_t)(g0 * 32 + nb) * 4096 + tid * 4;
        const uint32_t bd = smb + SMB_OFF(0) + tid * 16;
        cp_async16(bd,         bsrc);
        cp_async16(bd + 4096,  bsrc + 1024);
        cp_async16(bd + 8192,  bsrc + 2048);
        cp_async16(bd + 12288, bsrc + 3072);
        CP_COMMIT();
    }

    for (int gi = 0; gi < 4; gi++) {
        const int g = split * 4 + gi;

        // alpha (f16x2 broadcast) for B scaling: col_b = nq*32 + nt*8 + o
        uint32_t af[4];
        #pragma unroll
        for (int nt = 0; nt < 4; nt++) {
            const float a = __ldg(&alpha[g * OUT_F + nb * 128 + nq * 32 + nt * 8 + o]);
            asm("cvt.rn.f16x2.f32 %0, %1, %1;" : "=r"(af[nt]) : "f"(a));
        }

        CP_WAIT0();
        __syncthreads();

        if (gi < 3) {
            const int gn = g + 1;
            const int buf = (gi + 1) & 1;
            const uint4* asrc = g_xa + ((gn * 8 + aks) * 8 + mhalf * 4) * 32 + au * 4;
            const uint32_t ad = smb + SMA_OFF(buf) + aks * 2048 + au * 64;
            cp_async16(ad,      asrc);
            cp_async16(ad + 16, asrc + 1);
            cp_async16(ad + 32, asrc + 2);
            cp_async16(ad + 48, asrc + 3);
            const uint32_t* bsrc = g_qb + (size_t)(gn * 32 + nb) * 4096 + tid * 4;
            const uint32_t bd = smb + SMB_OFF(buf) + tid * 16;
            cp_async16(bd,         bsrc);
            cp_async16(bd + 4096,  bsrc + 1024);
            cp_async16(bd + 8192,  bsrc + 2048);
            cp_async16(bd + 12288, bsrc + 3072);
            CP_COMMIT();
        }

        const uint4* As = (const uint4*)(sm + SMA_OFF(gi & 1));
        const uint4* Bs = (const uint4*)(sm + SMB_OFF(gi & 1));

        #pragma unroll 4
        for (int ks = 0; ks < 8; ks++) {
            // --- A frags: 2 x LDS.128 (conflict-free contiguous) ---
            uint32_t A[2][4];
            #pragma unroll
            for (int mt = 0; mt < 2; mt++) {
                const uint4 h = As[ks * 128 + (wm * 2 + mt) * 32 + lane];
                A[mt][0] = h.x; A[mt][1] = h.y; A[mt][2] = h.z; A[mt][3] = h.w;
            }

            // --- B: ONE LDS.128 -> 4 words (nt), bytes [k0,k1,k8,k9] ---
            const uint4 w = Bs[ks * 128 + boff16];
            const uint32_t wn[4] = {w.x, w.y, w.z, w.w};

            // --- dequant+scale: PRMT -> q' f16x2, HMUL2 by alpha ---
            uint32_t B[4][2];
            #pragma unroll
            for (int nt = 0; nt < 4; nt++) {
                uint32_t b0 = __byte_perm(QLUT_A, QLUT_B,
                                          ((wn[nt] << 4)  & 0xF0F0u) | 0x0404u);
                uint32_t b1 = __byte_perm(QLUT_A, QLUT_B,
                                          ((wn[nt] >> 12) & 0xF0F0u) | 0x0404u);
                asm("mul.rn.f16x2 %0, %0, %1;" : "+r"(b0) : "r"(af[nt]));
                asm("mul.rn.f16x2 %0, %0, %1;" : "+r"(b1) : "r"(af[nt]));
                B[nt][0] = b0; B[nt][1] = b1;
            }

            // --- 8 fp16 HMMA per warp per kstep, accumulate into accT ---
            #pragma unroll
            for (int mt = 0; mt < 2; mt++)
                #pragma unroll
                for (int nt = 0; nt < 4; nt++)
                    asm volatile(
                        "mma.sync.aligned.m16n8k16.row.col.f32.f16.f16.f32 "
                        "{%0,%1,%2,%3}, {%4,%5,%6,%7}, {%8,%9}, {%0,%1,%2,%3};"
                        : "+f"(accT[mt][nt][0]), "+f"(accT[mt][nt][1]),
                          "+f"(accT[mt][nt][2]), "+f"(accT[mt][nt][3])
                        : "r"(A[mt][0]), "r"(A[mt][1]), "r"(A[mt][2]), "r"(A[mt][3]),
                          "r"(B[nt][0]), "r"(B[nt][1]));
        }

        // --- group epilogue: accT += (alpha+beta)·Xsum (rank-1 term) ---
        #pragma unroll
        for (int nt = 0; nt < 4; nt++) {
            const int col = nb * 128 + nq * 32 + nt * 8 + (lane & 3) * 2;
            const float c0 = __ldg(&alpha[g * OUT_F + col]) +
                             __ldg(&beta [g * OUT_F + col]);
            const float c1 = __ldg(&alpha[g * OUT_F + col + 1]) +
                             __ldg(&beta [g * OUT_F + col + 1]);
            #pragma unroll
            for (int mt = 0; mt < 2; mt++) {
                const int row = mhalf * 64 + wm * 32 + mt * 16 + (lane >> 2);
                const float x0 = __ldg(&g_xsum[g * 128 + row]);
                const float x1 = __ldg(&g_xsum[g * 128 + row + 8]);
                accT[mt][nt][0] = fmaf(c0, x0, accT[mt][nt][0]);
                accT[mt][nt][1] = fmaf(c1, x0, accT[mt][nt][1]);
                accT[mt][nt][2] = fmaf(c0, x1, accT[mt][nt][2]);
                accT[mt][nt][3] = fmaf(c1, x1, accT[mt][nt][3]);
            }
        }
    }

    // --- write K-split partials, plane = split (deterministic) ---
    float* dst = g_t_part + (size_t)split * (M_TOK * OUT_F);
    #pragma unroll
    for (int mt = 0; mt < 2; mt++) {
        const int row0 = mhalf * 64 + wm * 32 + mt * 16 + (lane >> 2);
        #pragma unroll
        for (int nt = 0; nt < 4; nt++) {
            const int col = nb * 128 + nq * 32 + nt * 8 + (lane & 3) * 2;
            *(float2*)&dst[ row0      * OUT_F + col] =
                make_float2(accT[mt][nt][0], accT[mt][nt][1]);
            *(float2*)&dst[(row0 + 8) * OUT_F + col] =
                make_float2(accT[mt][nt][2], accT[mt][nt][3]);
        }
    }
}

// ---------------------------------------------------------------------------
// Kernel 5: reduce 8 planes (coalesced float4)
// ---------------------------------------------------------------------------
__global__ __launch_bounds__(256)
void reduce_kernel() {
    const int i = blockIdx.x * 256 + threadIdx.x;        // 131072 float4s
    const float4* p = (const float4*)g_t_part;
    float4 s = p[i];
    #pragma unroll
    for (int pl = 1; pl < NPLANE; pl++) {
        const float4 t = p[pl * 131072 + i];
        s.x += t.x; s.y += t.y; s.z += t.z; s.w += t.w;
    }
    ((float4*)g_t_sum)[i] = s;
}

// ---------------------------------------------------------------------------
// Kernel 6: output permutation — coalesced writes, 4 independent gathers
// ---------------------------------------------------------------------------
__global__ __launch_bounds__(256)
void permute_kernel(const int* __restrict__ out_reorder, float* __restrict__ y) {
    const int t = blockIdx.x * 256 + threadIdx.x;        // 131072
    const int c = t & 4095;
    const int mq = t >> 12;                              // 0..31
    const int n = __ldg(&out_reorder[c]);
    #pragma unroll
    for (int u = 0; u < 4; u++) {
        const int m = mq * 4 + u;
        y[(size_t)m * OUT_F + c] = g_t_sum[(m << 12) | n];
    }
}

// ---------------------------------------------------------------------------
// Launch
// ---------------------------------------------------------------------------
extern "C" void kernel_launch(void* const* d_in, const int* in_sizes, int n_in,
                              void* d_out, int out_size) {
    const float* x           = (const float*)d_in[0];
    const int*   qweight     = (const int*)  d_in[1];
    const float* alpha       = (const float*)d_in[2];
    const float* beta        = (const float*)d_in[3];
    // d_in[4] = block_bitwidth (uniform 3, unused)
    const int*   offset      = (const int*)  d_in[5];
    const int*   in_reorder  = (const int*)  d_in[6];
    const int*   out_reorder = (const int*)  d_in[7];
    float* y = (float*)d_out;

    cudaFuncSetAttribute(bcq_gemm_kernel,
                         cudaFuncAttributeMaxDynamicSharedMemorySize, 65536);

    prep_x_kernel<<<256, 256>>>(x, in_reorder);
    xsum_kernel<<<128, 256>>>(x, in_reorder);
    repack_kernel<<<512, 256>>>(qweight, offset);
    bcq_gemm_kernel<<<dim3(32, 16), 256, 65536>>>(alpha, beta);
    reduce_kernel<<<512, 256>>>();
    permute_kernel<<<512, 256>>>(out_reorder, y);
}